// round 13
// baseline (speedup 1.0000x reference)
#include <cuda_runtime.h>
#include <cuda_fp16.h>
#include <math.h>
#include <stdint.h>

#define DIMV   1024
#define HEADS  16
#define DH     64
#define BATCH  4
#define SEQ    1024
#define BH     (BATCH*HEADS)
#define K_EFF  2048
#define KBYTES (K_EFF*2)

// ---------------- device scratch ----------------
__device__ __half g_Acat[(size_t)8192*K_EFF];        // [real rows 0..4095 | imag rows 4096..8191]
__device__ __half g_Wcat[(size_t)4096*K_EFF];        // 4 layers x 1024 rows: [Wr Wi]
__device__ __half g_Qpack[(size_t)BH*SEQ*128];       // [bh][n][qr | -qi]
__device__ __half g_Kpack[(size_t)BH*SEQ*128];       // [bh][n][kr | -ki]
__device__ __half g_Vp16[(size_t)BH*SEQ*128];        // [bh][n][vr | vi]

// ---------------- ptx helpers ----------------
__device__ __forceinline__ uint32_t smem_u32(const void* p) {
    uint32_t a;
    asm("{ .reg .u64 t; cvta.to.shared.u64 t, %1; cvt.u32.u64 %0, t; }" : "=r"(a) : "l"(p));
    return a;
}
__device__ __forceinline__ void cp16(uint32_t dst, const void* src) {
    asm volatile("cp.async.cg.shared.global [%0], [%1], 16;" :: "r"(dst), "l"(src) : "memory");
}
__device__ __forceinline__ void cp_commit() { asm volatile("cp.async.commit_group;" ::: "memory"); }
template<int N> __device__ __forceinline__ void cp_wait() {
    asm volatile("cp.async.wait_group %0;" :: "n"(N) : "memory");
}
__device__ __forceinline__ void ldsm4(uint32_t* r, uint32_t addr) {
    asm volatile("ldmatrix.sync.aligned.m8n8.x4.shared.b16 {%0,%1,%2,%3}, [%4];"
                 : "=r"(r[0]), "=r"(r[1]), "=r"(r[2]), "=r"(r[3]) : "r"(addr));
}
__device__ __forceinline__ void ldsm4t(uint32_t* r, uint32_t addr) {
    asm volatile("ldmatrix.sync.aligned.m8n8.x4.trans.shared.b16 {%0,%1,%2,%3}, [%4];"
                 : "=r"(r[0]), "=r"(r[1]), "=r"(r[2]), "=r"(r[3]) : "r"(addr));
}
__device__ __forceinline__ void mma16816(float* c, const uint32_t* a, uint32_t b0, uint32_t b1) {
    asm volatile(
        "mma.sync.aligned.m16n8k16.row.col.f32.f16.f16.f32 "
        "{%0,%1,%2,%3}, {%4,%5,%6,%7}, {%8,%9}, {%0,%1,%2,%3};"
        : "+f"(c[0]), "+f"(c[1]), "+f"(c[2]), "+f"(c[3])
        : "r"(a[0]), "r"(a[1]), "r"(a[2]), "r"(a[3]), "r"(b0), "r"(b1));
}
__device__ __forceinline__ uint32_t sw128(uint32_t off) { return off ^ ((off >> 3) & 0x70); }
__device__ __forceinline__ uint32_t hneg2u(uint32_t x) { return x ^ 0x80008000u; }

// ---------------- fp16 store helpers ----------------
__device__ __forceinline__ void st4h(__half* p, const float* v) {
    __half2 a = __floats2half2_rn(v[0], v[1]);
    __half2 b = __floats2half2_rn(v[2], v[3]);
    uint2 u;
    u.x = *(const uint32_t*)&a;
    u.y = *(const uint32_t*)&b;
    *(uint2*)p = u;
}
__device__ __forceinline__ void st4hn(__half* p, const float* v) {
    __half2 a = __floats2half2_rn(-v[0], -v[1]);
    __half2 b = __floats2half2_rn(-v[2], -v[3]);
    uint2 u;
    u.x = *(const uint32_t*)&a;
    u.y = *(const uint32_t*)&b;
    *(uint2*)p = u;
}

// ---------------- merged conversion: A + W operands ----------------
__global__ void conv_aw_kernel(const float* __restrict__ ar, const float* __restrict__ ai,
                               const float* __restrict__ Wr, const float* __restrict__ Wi)
{
    if (blockIdx.x < 4096) {
        const int idx = blockIdx.x * 256 + threadIdx.x;
        const int row = idx >> 8;
        const int c = (idx & 255) << 2;
        const size_t src = (size_t)row * 1024 + c;
        const float4 vr = *(const float4*)(ar + src);
        const float4 vi = *(const float4*)(ai + src);
        const float fr[4] = {vr.x, vr.y, vr.z, vr.w};
        const float fi[4] = {vi.x, vi.y, vi.z, vi.w};
        __half* Re = g_Acat + (size_t)row * K_EFF + c;
        __half* Im = g_Acat + (size_t)(row + 4096) * K_EFF + c;
        st4h (Re + 0,    fr);
        st4hn(Re + 1024, fi);
        st4h (Im + 0,    fi);
        st4h (Im + 1024, fr);
    } else {
        const int idx = (blockIdx.x - 4096) * 256 + threadIdx.x;
        const int row = idx >> 8;
        const int c = (idx & 255) << 2;
        const size_t src = (size_t)row * 1024 + c;
        const float4 vr = *(const float4*)(Wr + src);
        const float4 vi = *(const float4*)(Wi + src);
        const float fr[4] = {vr.x, vr.y, vr.z, vr.w};
        const float fi[4] = {vi.x, vi.y, vi.z, vi.w};
        __half* W = g_Wcat + (size_t)row * K_EFF + c;
        st4h(W + 0,    fr);
        st4h(W + 1024, fi);
    }
}

// ---------------- mma.sync projection GEMM (BM=64, 3 CTAs/SM, 24 warps) ----------------
#define BM 64
#define BN 128
#define BK 64
#define NITER (K_EFF/BK)     // 32
#define A_ST2 8192           // 64 rows * 128B
#define ST_SZ 24576          // A + B per stage
#define SMEM_GEMM (3*ST_SZ)  // 73728

__device__ __forceinline__ void load_stage(uint32_t sbase, int s, int kt, int tid,
                                           const __half* Ab, const __half* Bb)
{
    const char* aSrc = (const char*)Ab + (size_t)kt * (BK * 2);
    const char* bSrc = (const char*)Bb + (size_t)kt * (BK * 2);
    const uint32_t aDst = sbase + s * ST_SZ;
    const uint32_t bDst = aDst + A_ST2;
#pragma unroll
    for (int i = 0; i < 6; i++) {
        const int q = tid + i * 256;         // 0..1535 : 192 rows x 8 chunks
        const int row = q >> 3, cc = q & 7;
        if (row < 64) {
            cp16(aDst + sw128(row * 128 + cc * 16), aSrc + (size_t)row * KBYTES + cc * 16);
        } else {
            const int r2 = row - 64;
            cp16(bDst + sw128(r2 * 128 + cc * 16), bSrc + (size_t)r2 * KBYTES + cc * 16);
        }
    }
}

// epilogue: mode 0 writes Qpack/Kpack/Vp16 fp16; mode 1 writes final fp32 planes
__device__ __forceinline__ void epi_store(int mode, int gm, int gc,
                                          float v0, float v1,
                                          const float* biasR, const float* biasI,
                                          float* outR, float* outI)
{
    const int plane = gm >> 12;
    const int m = gm & 4095;
    const int b = m >> 10, n = m & 1023;
    const float* bias = plane ? biasI : biasR;
    const float f0 = v0 + bias[gc];
    const float f1 = v1 + bias[gc + 1];
    if (mode == 0) {
        const int layer = gc >> 10;
        const int cw = gc & 1023;
        const int h = cw >> 6, d = cw & 63;
        const int bh = b * HEADS + h;
        const __half2 hp = __floats2half2_rn(f0, f1);
        if (layer == 2) {
            __half* dst = g_Vp16 + ((size_t)bh * SEQ + n) * 128 + plane * 64 + d;
            *(uint32_t*)dst = *(const uint32_t*)&hp;
        } else {
            const __half2 hs = plane ? __hneg2(hp) : hp;
            __half* base = (layer == 0) ? g_Qpack : g_Kpack;
            __half* dst = base + ((size_t)bh * SEQ + n) * 128 + plane * 64 + d;
            *(uint32_t*)dst = *(const uint32_t*)&hs;
        }
    } else {
        float* base = plane ? outI : outR;
        float2 v; v.x = f0; v.y = f1;
        *(float2*)(base + (size_t)m * 1024 + gc) = v;
    }
}

__global__ void __launch_bounds__(256, 3) mma_gemm(
    const float* __restrict__ biasR, const float* __restrict__ biasI,
    float* __restrict__ outR, float* __restrict__ outI, int mode)
{
    extern __shared__ char smem[];
    const uint32_t sbase = smem_u32(smem);
    const int tid = threadIdx.x;
    const int lane = tid & 31;
    const int wid = tid >> 5;
    const int wm = wid & 3;      // warp rows: wm*16
    const int wn = wid >> 2;     // warp cols: wn*64

    const __half* Ab = g_Acat + (size_t)blockIdx.y * BM * K_EFF;
    const __half* Bb = g_Wcat + (mode ? (size_t)3072 * K_EFF : 0)
                              + (size_t)blockIdx.x * BN * K_EFF;

    float acc[8][4];
#pragma unroll
    for (int nt = 0; nt < 8; nt++)
#pragma unroll
        for (int r = 0; r < 4; r++) acc[nt][r] = 0.f;

    load_stage(sbase, 0, 0, tid, Ab, Bb); cp_commit();
    load_stage(sbase, 1, 1, tid, Ab, Bb); cp_commit();

    const int lr_ = lane & 15;
    const int lc16 = (lane >> 4) * 16;

    for (int kt = 0; kt < NITER; kt++) {
        cp_wait<1>();
        __syncthreads();
        const int slot = kt % 3;
        const uint32_t aB = sbase + slot * ST_SZ;
        const uint32_t bB = aB + A_ST2;
#pragma unroll
        for (int ks = 0; ks < 4; ks++) {
            const uint32_t cb = ks * 32 + lc16;
            uint32_t af[4], bf[4][4];
            {
                const uint32_t off = (uint32_t)(wm * 16 + lr_) * 128 + cb;
                ldsm4(af, aB + sw128(off));
            }
#pragma unroll
            for (int pr = 0; pr < 4; pr++) {
                const uint32_t off = (uint32_t)(wn * 64 + pr * 16 + lr_) * 128 + cb;
                ldsm4(bf[pr], bB + sw128(off));
            }
#pragma unroll
            for (int nt = 0; nt < 8; nt++)
                mma16816(acc[nt], af,
                         bf[nt >> 1][nt & 1], bf[nt >> 1][(nt & 1) + 2]);
        }
        const int pk = kt + 2;
        if (pk < NITER) load_stage(sbase, pk % 3, pk, tid, Ab, Bb);
        cp_commit();
    }

    const int blockRow = blockIdx.y * BM;
    const int blockCol = blockIdx.x * BN;
    {
        const int gr0 = blockRow + wm * 16 + (lane >> 2);
#pragma unroll
        for (int nt = 0; nt < 8; nt++) {
            const int gc = blockCol + wn * 64 + nt * 8 + (lane & 3) * 2;
            epi_store(mode, gr0,     gc, acc[nt][0], acc[nt][1], biasR, biasI, outR, outI);
            epi_store(mode, gr0 + 8, gc, acc[nt][2], acc[nt][3], biasR, biasI, outR, outI);
        }
    }
}

// =================== tensor-core attention (fp16, 512 threads, 3 syncs/kt) ===================
// smem: Q 32KB | K 2x16KB | V 2x16KB | P 16KB | rowsum 1KB  (~113KB)
#define SQ_OFF 0
#define SK_OFF 32768
#define SV_OFF (SK_OFF + 2*16384)
#define SP_OFF (SV_OFF + 2*16384)
#define SRS_OFF (SP_OFF + 16384)
#define ATTN2_SMEM (SRS_OFF + 1024)

__global__ void __launch_bounds__(512, 1) attn2_kernel()
{
    extern __shared__ char sm[];
    const uint32_t sb = smem_u32(sm);
    const uint32_t sQ = sb + SQ_OFF;
    const uint32_t sK = sb + SK_OFF;
    const uint32_t sV = sb + SV_OFF;
    const uint32_t sP = sb + SP_OFF;
    float* sRS = (float*)(sm + SRS_OFF);

    const int tid = threadIdx.x;
    const int lane = tid & 31;
    const int wid = tid >> 5;
    const int wm = wid & 7;
    const int wn = wid >> 3;
    const int bh = blockIdx.y;
    const int n0 = blockIdx.x * 128;

    const char* Qg = (const char*)(g_Qpack + ((size_t)bh * SEQ + n0) * 128);
    const char* Kg = (const char*)(g_Kpack + (size_t)bh * SEQ * 128);
    const char* Vg = (const char*)(g_Vp16 + (size_t)bh * SEQ * 128);

#pragma unroll
    for (int i = 0; i < 4; i++) {
        const int q = tid + i * 512;
        const int row = q >> 4, cc = q & 15;
        const int ch = cc >> 3, w = cc & 7;
        cp16(sQ + ch * 16384 + sw128(row * 128 + w * 16),
             Qg + (size_t)row * 256 + cc * 16);
    }
    cp_commit();

#define LOAD_K(ktile, buf) do { \
    _Pragma("unroll") \
    for (int i = 0; i < 2; i++) { \
        const int q = tid + i * 512; \
        const int row = q >> 4, cc = q & 15; \
        const int ch = cc >> 3, w = cc & 7; \
        cp16(sK + (buf) * 16384 + ch * 8192 + sw128(row * 128 + w * 16), \
             Kg + (size_t)((ktile) * 64 + row) * 256 + cc * 16); \
    } \
    cp_commit(); } while (0)

#define LOAD_V(ktile, buf) do { \
    _Pragma("unroll") \
    for (int i = 0; i < 2; i++) { \
        const int q = tid + i * 512; \
        const int row = q >> 4, cc = q & 15; \
        const int ch = cc >> 3, w = cc & 7; \
        cp16(sV + (buf) * 16384 + ch * 8192 + sw128(row * 128 + w * 16), \
             Vg + (size_t)((ktile) * 64 + row) * 256 + cc * 16); \
    } \
    cp_commit(); } while (0)

    LOAD_K(0, 0);
    LOAD_V(0, 0);
    LOAD_K(1, 1);
    LOAD_V(1, 1);

    float accO[8][4];
#pragma unroll
    for (int nt = 0; nt < 8; nt++)
#pragma unroll
        for (int e = 0; e < 4; e++) accO[nt][e] = 0.f;
    float rs[2] = {0.f, 0.f};

    const int lr_ = lane & 15;
    const int lc16 = (lane >> 4) * 16;
    const int lr8 = lane & 7;
    const int lgrp = lane >> 3;

    for (int kt = 0; kt < 16; kt++) {
        const int buf = kt & 1;
        // K(kt) ready
        if (kt <= 14) cp_wait<3>(); else cp_wait<1>();
        __syncthreads();

        float accR[4][4], accI[4][4];
#pragma unroll
        for (int nt = 0; nt < 4; nt++)
#pragma unroll
            for (int e = 0; e < 4; e++) { accR[nt][e] = 0.f; accI[nt][e] = 0.f; }

        const uint32_t kBase = sK + buf * 16384;
#pragma unroll
        for (int dks = 0; dks < 4; dks++) {
            const uint32_t w = dks * 32 + lc16;
            uint32_t qf0[4], qf1[4], qneg[4];
            const uint32_t qoff = sw128((uint32_t)(wm * 16 + lr_) * 128 + w);
            ldsm4(qf0, sQ + qoff);
            ldsm4(qf1, sQ + 16384 + qoff);
#pragma unroll
            for (int e = 0; e < 4; e++) qneg[e] = hneg2u(qf1[e]);

            uint32_t b0[2][4], b1[2][4];
#pragma unroll
            for (int pr = 0; pr < 2; pr++) {
                const uint32_t koff = sw128((uint32_t)(wn * 32 + pr * 16 + lr_) * 128 + w);
                ldsm4(b0[pr], kBase + koff);
                ldsm4(b1[pr], kBase + 8192 + koff);
            }
#pragma unroll
            for (int nt = 0; nt < 4; nt++) {
                const uint32_t br0 = b0[nt >> 1][nt & 1], br1 = b0[nt >> 1][(nt & 1) + 2];
                const uint32_t bi0 = b1[nt >> 1][nt & 1], bi1 = b1[nt >> 1][(nt & 1) + 2];
                mma16816(accR[nt], qf0,  br0, br1);
                mma16816(accR[nt], qf1,  bi0, bi1);
                mma16816(accI[nt], qneg, br0, br1);
                mma16816(accI[nt], qf0,  bi0, bi1);
            }
        }

        // ---- softmax -> P (fp16); no barrier needed before (register-only inputs) ----
#pragma unroll
        for (int nt = 0; nt < 4; nt++) {
            float p[4];
#pragma unroll
            for (int e = 0; e < 4; e++) {
                const float srv = accR[nt][e];
                const float siv = accI[nt][e];
                p[e] = __expf(sqrtf(srv * srv + siv * siv) * 0.125f);
            }
            rs[0] += p[0] + p[1];
            rs[1] += p[2] + p[3];
            const int keyb = (wn * 32 + nt * 8 + (lane & 3) * 2) * 2;
            const int row0 = wm * 16 + (lane >> 2);
#pragma unroll
            for (int half = 0; half < 2; half++) {
                const __half2 hp = __floats2half2_rn(p[half * 2], p[half * 2 + 1]);
                const uint32_t off = (uint32_t)(row0 + half * 8) * 128 + keyb;
                *(uint32_t*)(sm + SP_OFF + sw128(off)) = *(const uint32_t*)&hp;
            }
        }

        // V(kt) ready + P visible + all warps done with sK(buf)  — single barrier
        if (kt <= 14) cp_wait<2>(); else cp_wait<0>();
        __syncthreads();
        if (kt + 2 <= 15) LOAD_K(kt + 2, buf);

        // ---- PV ----
        const uint32_t vBase = sV + buf * 16384;
#pragma unroll
        for (int ks = 0; ks < 4; ks++) {
            const uint32_t cb = ks * 32 + lc16;
            uint32_t af[4];
            {
                const uint32_t off = (uint32_t)(wm * 16 + lr_) * 128 + cb;
                ldsm4(af, sP + sw128(off));
            }
#pragma unroll
            for (int pr = 0; pr < 4; pr++) {
                const uint32_t colByte = (uint32_t)(wn * 128 + pr * 32 + ((lgrp >> 1) << 4));
                const uint32_t vrow = (uint32_t)(ks * 16 + ((lgrp & 1) << 3) + lr8);
                uint32_t bt[4];
                ldsm4t(bt, vBase + (colByte >> 7) * 8192 + sw128(vrow * 128 + (colByte & 127)));
                mma16816(accO[2 * pr],     af, bt[0], bt[1]);
                mma16816(accO[2 * pr + 1], af, bt[2], bt[3]);
            }
        }
        __syncthreads();
        if (kt + 2 <= 15) LOAD_V(kt + 2, buf);
    }

    // ---- rowsum reduction ----
#pragma unroll
    for (int e = 0; e < 2; e++) {
        rs[e] += __shfl_xor_sync(0xffffffffu, rs[e], 1);
        rs[e] += __shfl_xor_sync(0xffffffffu, rs[e], 2);
    }
    if ((lane & 3) == 0) {
#pragma unroll
        for (int e = 0; e < 2; e++)
            sRS[wn * 128 + wm * 16 + (lane >> 2) + 8 * e] = rs[e];
    }
    __syncthreads();

    // ---- normalize + write g_Acat rows ----
    const int b = bh >> 4, h = bh & 15;
#pragma unroll
    for (int half = 0; half < 2; half++) {
        const int row = wm * 16 + (lane >> 2) + 8 * half;
        const float inv = 1.0f / (sRS[row] + sRS[128 + row]);
        const int m = b * 1024 + (n0 + row);
        __half* ReRow = g_Acat + (size_t)m * K_EFF;
        __half* ImRow = g_Acat + (size_t)(m + 4096) * K_EFF;
#pragma unroll
        for (int nt = 0; nt < 8; nt++) {
            const int col = wn * 64 + nt * 8 + (lane & 3) * 2;
            const int d = col & 63;
            const int c = h * 64 + d;
            const float v0 = accO[nt][half * 2] * inv;
            const float v1 = accO[nt][half * 2 + 1] * inv;
            const __half2 hp = __floats2half2_rn(v0, v1);
            if (col < 64) {
                *(uint32_t*)(ReRow + c) = *(const uint32_t*)&hp;
                *(uint32_t*)(ImRow + 1024 + c) = *(const uint32_t*)&hp;
            } else {
                const __half2 hn = __hneg2(hp);
                *(uint32_t*)(ReRow + 1024 + c) = *(const uint32_t*)&hn;
                *(uint32_t*)(ImRow + c) = *(const uint32_t*)&hp;
            }
        }
    }
}

// =================== launcher ===================
extern "C" void kernel_launch(void* const* d_in, const int* in_sizes, int n_in,
                              void* d_out, int out_size)
{
    const float* xr = (const float*)d_in[0];
    const float* xi = (const float*)d_in[1];
    const float* Wr = (const float*)d_in[2];
    const float* Wi = (const float*)d_in[3];
    const float* br = (const float*)d_in[4];
    const float* bi = (const float*)d_in[5];

    float* outR = (float*)d_out;
    float* outI = outR + (size_t)BATCH * SEQ * DIMV;

    cudaFuncSetAttribute(mma_gemm, cudaFuncAttributeMaxDynamicSharedMemorySize, SMEM_GEMM);
    cudaFuncSetAttribute(attn2_kernel, cudaFuncAttributeMaxDynamicSharedMemorySize, ATTN2_SMEM);

    // build fp16 A and W operands (merged)
    conv_aw_kernel<<<8192, 256>>>(xr, xi, Wr, Wi);

    // fused QKV projection; epilogue emits Qpack/Kpack/Vp16 fp16 directly
    mma_gemm<<<dim3(3072 / BN, 8192 / BM), 256, SMEM_GEMM>>>(br, bi, nullptr, nullptr, 0);

    // tensor-core attention (512 threads); epilogue writes g_Acat directly
    attn2_kernel<<<dim3(SEQ / 128, BH), 512, ATTN2_SMEM>>>();

    // output projection -> d_out
    mma_gemm<<<dim3(1024 / BN, 8192 / BM), 256, SMEM_GEMM>>>(br + 3 * DIMV, bi + 3 * DIMV,
                                                             outR, outI, 1);
}

// round 14
// speedup vs baseline: 1.1224x; 1.1224x over previous
#include <cuda_runtime.h>
#include <cuda_fp16.h>
#include <math.h>
#include <stdint.h>

#define DIMV   1024
#define HEADS  16
#define DH     64
#define BATCH  4
#define SEQ    1024
#define BH     (BATCH*HEADS)
#define K_EFF  2048
#define KBYTES (K_EFF*2)

// ---------------- device scratch ----------------
__device__ __half g_Acat[(size_t)8192*K_EFF];        // [real rows 0..4095 | imag rows 4096..8191]
__device__ __half g_Wcat[(size_t)4096*K_EFF];        // 4 layers x 1024 rows: [Wr Wi]
__device__ __half g_Qpack[(size_t)BH*SEQ*128];       // [bh][n][qr | -qi]
__device__ __half g_Kpack[(size_t)BH*SEQ*128];       // [bh][n][kr | -ki]
__device__ __half g_Vp16[(size_t)BH*SEQ*128];        // [bh][n][vr | vi]

// ---------------- ptx helpers ----------------
__device__ __forceinline__ uint32_t smem_u32(const void* p) {
    uint32_t a;
    asm("{ .reg .u64 t; cvta.to.shared.u64 t, %1; cvt.u32.u64 %0, t; }" : "=r"(a) : "l"(p));
    return a;
}
__device__ __forceinline__ void cp16(uint32_t dst, const void* src) {
    asm volatile("cp.async.cg.shared.global [%0], [%1], 16;" :: "r"(dst), "l"(src) : "memory");
}
__device__ __forceinline__ void cp_commit() { asm volatile("cp.async.commit_group;" ::: "memory"); }
template<int N> __device__ __forceinline__ void cp_wait() {
    asm volatile("cp.async.wait_group %0;" :: "n"(N) : "memory");
}
__device__ __forceinline__ void ldsm4(uint32_t* r, uint32_t addr) {
    asm volatile("ldmatrix.sync.aligned.m8n8.x4.shared.b16 {%0,%1,%2,%3}, [%4];"
                 : "=r"(r[0]), "=r"(r[1]), "=r"(r[2]), "=r"(r[3]) : "r"(addr));
}
__device__ __forceinline__ void ldsm4t(uint32_t* r, uint32_t addr) {
    asm volatile("ldmatrix.sync.aligned.m8n8.x4.trans.shared.b16 {%0,%1,%2,%3}, [%4];"
                 : "=r"(r[0]), "=r"(r[1]), "=r"(r[2]), "=r"(r[3]) : "r"(addr));
}
__device__ __forceinline__ void mma16816(float* c, const uint32_t* a, uint32_t b0, uint32_t b1) {
    asm volatile(
        "mma.sync.aligned.m16n8k16.row.col.f32.f16.f16.f32 "
        "{%0,%1,%2,%3}, {%4,%5,%6,%7}, {%8,%9}, {%0,%1,%2,%3};"
        : "+f"(c[0]), "+f"(c[1]), "+f"(c[2]), "+f"(c[3])
        : "r"(a[0]), "r"(a[1]), "r"(a[2]), "r"(a[3]), "r"(b0), "r"(b1));
}
__device__ __forceinline__ uint32_t sw128(uint32_t off) { return off ^ ((off >> 3) & 0x70); }
__device__ __forceinline__ uint32_t hneg2u(uint32_t x) { return x ^ 0x80008000u; }

// ---------------- fp16 store helpers ----------------
__device__ __forceinline__ void st4h(__half* p, const float* v) {
    __half2 a = __floats2half2_rn(v[0], v[1]);
    __half2 b = __floats2half2_rn(v[2], v[3]);
    uint2 u;
    u.x = *(const uint32_t*)&a;
    u.y = *(const uint32_t*)&b;
    *(uint2*)p = u;
}
__device__ __forceinline__ void st4hn(__half* p, const float* v) {
    __half2 a = __floats2half2_rn(-v[0], -v[1]);
    __half2 b = __floats2half2_rn(-v[2], -v[3]);
    uint2 u;
    u.x = *(const uint32_t*)&a;
    u.y = *(const uint32_t*)&b;
    *(uint2*)p = u;
}

// ---------------- merged conversion: A + W operands ----------------
__global__ void conv_aw_kernel(const float* __restrict__ ar, const float* __restrict__ ai,
                               const float* __restrict__ Wr, const float* __restrict__ Wi)
{
    if (blockIdx.x < 4096) {
        const int idx = blockIdx.x * 256 + threadIdx.x;
        const int row = idx >> 8;
        const int c = (idx & 255) << 2;
        const size_t src = (size_t)row * 1024 + c;
        const float4 vr = *(const float4*)(ar + src);
        const float4 vi = *(const float4*)(ai + src);
        const float fr[4] = {vr.x, vr.y, vr.z, vr.w};
        const float fi[4] = {vi.x, vi.y, vi.z, vi.w};
        __half* Re = g_Acat + (size_t)row * K_EFF + c;
        __half* Im = g_Acat + (size_t)(row + 4096) * K_EFF + c;
        st4h (Re + 0,    fr);
        st4hn(Re + 1024, fi);
        st4h (Im + 0,    fi);
        st4h (Im + 1024, fr);
    } else {
        const int idx = (blockIdx.x - 4096) * 256 + threadIdx.x;
        const int row = idx >> 8;
        const int c = (idx & 255) << 2;
        const size_t src = (size_t)row * 1024 + c;
        const float4 vr = *(const float4*)(Wr + src);
        const float4 vi = *(const float4*)(Wi + src);
        const float fr[4] = {vr.x, vr.y, vr.z, vr.w};
        const float fi[4] = {vi.x, vi.y, vi.z, vi.w};
        __half* W = g_Wcat + (size_t)row * K_EFF + c;
        st4h(W + 0,    fr);
        st4h(W + 1024, fi);
    }
}

// ---------------- mma.sync projection GEMM (R11 form — FROZEN) ----------------
#define BM 128
#define BN 128
#define BK 64
#define NITER (K_EFF/BK)     // 32
#define A_ST  16384
#define ST_SZ 32768
#define SMEM_GEMM (3*ST_SZ)

__device__ __forceinline__ void load_stage(uint32_t sbase, int s, int kt, int tid,
                                           const __half* Ab, const __half* Bb)
{
    const char* aSrc = (const char*)Ab + (size_t)kt * (BK * 2);
    const char* bSrc = (const char*)Bb + (size_t)kt * (BK * 2);
    const uint32_t aDst = sbase + s * ST_SZ;
    const uint32_t bDst = aDst + A_ST;
#pragma unroll
    for (int i = 0; i < 4; i++) {
        const int q = tid + i * 256;
        const int row = q >> 3, cc = q & 7;
        const uint32_t sw = sw128(row * 128 + cc * 16);
        cp16(aDst + sw, aSrc + (size_t)row * KBYTES + cc * 16);
        cp16(bDst + sw, bSrc + (size_t)row * KBYTES + cc * 16);
    }
}

// epilogue: mode 0 writes Qpack/Kpack/Vp16 fp16; mode 1 writes final fp32 planes
__device__ __forceinline__ void epi_store(int mode, int gm, int gc,
                                          float v0, float v1,
                                          const float* biasR, const float* biasI,
                                          float* outR, float* outI)
{
    const int plane = gm >> 12;
    const int m = gm & 4095;
    const int b = m >> 10, n = m & 1023;
    const float* bias = plane ? biasI : biasR;
    const float f0 = v0 + bias[gc];
    const float f1 = v1 + bias[gc + 1];
    if (mode == 0) {
        const int layer = gc >> 10;
        const int cw = gc & 1023;
        const int h = cw >> 6, d = cw & 63;
        const int bh = b * HEADS + h;
        const __half2 hp = __floats2half2_rn(f0, f1);
        if (layer == 2) {
            __half* dst = g_Vp16 + ((size_t)bh * SEQ + n) * 128 + plane * 64 + d;
            *(uint32_t*)dst = *(const uint32_t*)&hp;
        } else {
            const __half2 hs = plane ? __hneg2(hp) : hp;
            __half* base = (layer == 0) ? g_Qpack : g_Kpack;
            __half* dst = base + ((size_t)bh * SEQ + n) * 128 + plane * 64 + d;
            *(uint32_t*)dst = *(const uint32_t*)&hs;
        }
    } else {
        float* base = plane ? outI : outR;
        float2 v; v.x = f0; v.y = f1;
        *(float2*)(base + (size_t)m * 1024 + gc) = v;
    }
}

__global__ void __launch_bounds__(256, 2) mma_gemm(
    const float* __restrict__ biasR, const float* __restrict__ biasI,
    float* __restrict__ outR, float* __restrict__ outI, int mode)
{
    extern __shared__ char smem[];
    const uint32_t sbase = smem_u32(smem);
    const int tid = threadIdx.x;
    const int lane = tid & 31;
    const int wid = tid >> 5;
    const int wm = wid & 3;
    const int wn = wid >> 2;

    const __half* Ab = g_Acat + (size_t)blockIdx.y * BM * K_EFF;
    const __half* Bb = g_Wcat + (mode ? (size_t)3072 * K_EFF : 0)
                              + (size_t)blockIdx.x * BN * K_EFF;

    float acc[2][8][4];
#pragma unroll
    for (int mt = 0; mt < 2; mt++)
#pragma unroll
        for (int nt = 0; nt < 8; nt++)
#pragma unroll
            for (int r = 0; r < 4; r++) acc[mt][nt][r] = 0.f;

    load_stage(sbase, 0, 0, tid, Ab, Bb); cp_commit();
    load_stage(sbase, 1, 1, tid, Ab, Bb); cp_commit();

    const int lr_ = lane & 15;
    const int lc16 = (lane >> 4) * 16;

    for (int kt = 0; kt < NITER; kt++) {
        cp_wait<1>();
        __syncthreads();
        const int slot = kt % 3;
        const uint32_t aB = sbase + slot * ST_SZ;
        const uint32_t bB = aB + A_ST;
#pragma unroll
        for (int ks = 0; ks < 4; ks++) {
            const uint32_t cb = ks * 32 + lc16;
            uint32_t af[2][4], bf[4][4];
#pragma unroll
            for (int mt = 0; mt < 2; mt++) {
                const uint32_t off = (uint32_t)(wm * 32 + mt * 16 + lr_) * 128 + cb;
                ldsm4(af[mt], aB + sw128(off));
            }
#pragma unroll
            for (int pr = 0; pr < 4; pr++) {
                const uint32_t off = (uint32_t)(wn * 64 + pr * 16 + lr_) * 128 + cb;
                ldsm4(bf[pr], bB + sw128(off));
            }
#pragma unroll
            for (int mt = 0; mt < 2; mt++)
#pragma unroll
                for (int nt = 0; nt < 8; nt++)
                    mma16816(acc[mt][nt], af[mt],
                             bf[nt >> 1][nt & 1], bf[nt >> 1][(nt & 1) + 2]);
        }
        const int pk = kt + 2;
        if (pk < NITER) load_stage(sbase, pk % 3, pk, tid, Ab, Bb);
        cp_commit();
    }

    const int blockRow = blockIdx.y * BM;
    const int blockCol = blockIdx.x * BN;
#pragma unroll
    for (int mt = 0; mt < 2; mt++) {
        const int gr0 = blockRow + wm * 32 + mt * 16 + (lane >> 2);
#pragma unroll
        for (int nt = 0; nt < 8; nt++) {
            const int gc = blockCol + wn * 64 + nt * 8 + (lane & 3) * 2;
            epi_store(mode, gr0,     gc, acc[mt][nt][0], acc[mt][nt][1], biasR, biasI, outR, outI);
            epi_store(mode, gr0 + 8, gc, acc[mt][nt][2], acc[mt][nt][3], biasR, biasI, outR, outI);
        }
    }
}

// =================== tensor-core attention (fp16, 256 thr / 64q, 2 CTAs/SM) ===================
// smem: Q 16KB | K 2x16KB | V 2x16KB | P 8KB | rowsum 512B  (~88.5KB -> 2 CTAs/SM)
#define SQ_OFF 0
#define SK_OFF 16384
#define SV_OFF (SK_OFF + 2*16384)
#define SP_OFF (SV_OFF + 2*16384)
#define SRS_OFF (SP_OFF + 8192)
#define ATTN2_SMEM (SRS_OFF + 512)

__global__ void __launch_bounds__(256, 2) attn2_kernel()
{
    extern __shared__ char sm[];
    const uint32_t sb = smem_u32(sm);
    const uint32_t sQ = sb + SQ_OFF;
    const uint32_t sK = sb + SK_OFF;
    const uint32_t sV = sb + SV_OFF;
    const uint32_t sP = sb + SP_OFF;
    float* sRS = (float*)(sm + SRS_OFF);

    const int tid = threadIdx.x;
    const int lane = tid & 31;
    const int wid = tid >> 5;     // 0..7
    const int wm = wid & 3;       // 16-query row group: rows wm*16..wm*16+15
    const int wn = wid >> 2;      // 0/1: key half (S) / dh-col half (PV)
    const int bh = blockIdx.y;
    const int n0 = blockIdx.x * 64;

    const char* Qg = (const char*)(g_Qpack + ((size_t)bh * SEQ + n0) * 128);
    const char* Kg = (const char*)(g_Kpack + (size_t)bh * SEQ * 128);
    const char* Vg = (const char*)(g_Vp16 + (size_t)bh * SEQ * 128);

    // Q: 64 rows x 256B (two 8KB chunks)
#pragma unroll
    for (int i = 0; i < 4; i++) {
        const int q = tid + i * 256;
        const int row = q >> 4, cc = q & 15;
        const int ch = cc >> 3, w = cc & 7;
        cp16(sQ + ch * 8192 + sw128(row * 128 + w * 16),
             Qg + (size_t)row * 256 + cc * 16);
    }
    cp_commit();

// K tile: 64 key rows x 256B -> two 8KB chunks (kr | -ki)
#define LOAD_K(ktile, buf) do { \
    _Pragma("unroll") \
    for (int i = 0; i < 4; i++) { \
        const int q = tid + i * 256; \
        const int row = q >> 4, cc = q & 15; \
        const int ch = cc >> 3, w = cc & 7; \
        cp16(sK + (buf) * 16384 + ch * 8192 + sw128(row * 128 + w * 16), \
             Kg + (size_t)((ktile) * 64 + row) * 256 + cc * 16); \
    } \
    cp_commit(); } while (0)

// V tile: 64 key rows x 256B -> two 8KB chunks
#define LOAD_V(ktile, buf) do { \
    _Pragma("unroll") \
    for (int i = 0; i < 4; i++) { \
        const int q = tid + i * 256; \
        const int row = q >> 4, cc = q & 15; \
        const int ch = cc >> 3, w = cc & 7; \
        cp16(sV + (buf) * 16384 + ch * 8192 + sw128(row * 128 + w * 16), \
             Vg + (size_t)((ktile) * 64 + row) * 256 + cc * 16); \
    } \
    cp_commit(); } while (0)

    LOAD_K(0, 0);
    LOAD_V(0, 0);
    LOAD_K(1, 1);
    LOAD_V(1, 1);

    float accO[8][4];
#pragma unroll
    for (int nt = 0; nt < 8; nt++)
#pragma unroll
        for (int e = 0; e < 4; e++) accO[nt][e] = 0.f;
    float rs[2] = {0.f, 0.f};

    const int lr_ = lane & 15;
    const int lc16 = (lane >> 4) * 16;
    const int lr8 = lane & 7;
    const int lgrp = lane >> 3;

    for (int kt = 0; kt < 16; kt++) {
        const int buf = kt & 1;
        if (kt <= 14) cp_wait<3>(); else cp_wait<1>();
        __syncthreads();

        float accR[4][4], accI[4][4];
#pragma unroll
        for (int nt = 0; nt < 4; nt++)
#pragma unroll
            for (int e = 0; e < 4; e++) { accR[nt][e] = 0.f; accI[nt][e] = 0.f; }

        const uint32_t kBase = sK + buf * 16384;
#pragma unroll
        for (int dks = 0; dks < 4; dks++) {
            const uint32_t w = dks * 32 + lc16;
            uint32_t qf0[4], qf1[4], qneg[4];
            const uint32_t qoff = sw128((uint32_t)(wm * 16 + lr_) * 128 + w);
            ldsm4(qf0, sQ + qoff);                   // qr slice
            ldsm4(qf1, sQ + 8192 + qoff);            // -qi slice
#pragma unroll
            for (int e = 0; e < 4; e++) qneg[e] = hneg2u(qf1[e]);

            uint32_t b0[2][4], b1[2][4];
#pragma unroll
            for (int pr = 0; pr < 2; pr++) {
                const uint32_t koff = sw128((uint32_t)(wn * 32 + pr * 16 + lr_) * 128 + w);
                ldsm4(b0[pr], kBase + koff);
                ldsm4(b1[pr], kBase + 8192 + koff);
            }
#pragma unroll
            for (int nt = 0; nt < 4; nt++) {
                const uint32_t br0 = b0[nt >> 1][nt & 1], br1 = b0[nt >> 1][(nt & 1) + 2];
                const uint32_t bi0 = b1[nt >> 1][nt & 1], bi1 = b1[nt >> 1][(nt & 1) + 2];
                mma16816(accR[nt], qf0,  br0, br1);
                mma16816(accR[nt], qf1,  bi0, bi1);
                mma16816(accI[nt], qneg, br0, br1);
                mma16816(accI[nt], qf0,  bi0, bi1);
            }
        }
        __syncthreads();
        if (kt + 2 <= 15) LOAD_K(kt + 2, buf);

        // ---- softmax -> P (fp16) ----
#pragma unroll
        for (int nt = 0; nt < 4; nt++) {
            float p[4];
#pragma unroll
            for (int e = 0; e < 4; e++) {
                const float srv = accR[nt][e];
                const float siv = accI[nt][e];
                p[e] = __expf(sqrtf(srv * srv + siv * siv) * 0.125f);
            }
            rs[0] += p[0] + p[1];
            rs[1] += p[2] + p[3];
            const int keyb = (wn * 32 + nt * 8 + (lane & 3) * 2) * 2;
            const int row0 = wm * 16 + (lane >> 2);
#pragma unroll
            for (int half = 0; half < 2; half++) {
                const __half2 hp = __floats2half2_rn(p[half * 2], p[half * 2 + 1]);
                const uint32_t off = (uint32_t)(row0 + half * 8) * 128 + keyb;
                *(uint32_t*)(sm + SP_OFF + sw128(off)) = *(const uint32_t*)&hp;
            }
        }
        __syncthreads();

        if (kt <= 13) cp_wait<3>();
        else if (kt == 14) cp_wait<2>();
        else cp_wait<0>();
        __syncthreads();

        // ---- PV ----
        const uint32_t vBase = sV + buf * 16384;
#pragma unroll
        for (int ks = 0; ks < 4; ks++) {
            const uint32_t cb = ks * 32 + lc16;
            uint32_t af[4];
            {
                const uint32_t off = (uint32_t)(wm * 16 + lr_) * 128 + cb;
                ldsm4(af, sP + sw128(off));
            }
#pragma unroll
            for (int pr = 0; pr < 4; pr++) {
                const uint32_t colByte = (uint32_t)(wn * 128 + pr * 32 + ((lgrp >> 1) << 4));
                const uint32_t vrow = (uint32_t)(ks * 16 + ((lgrp & 1) << 3) + lr8);
                uint32_t bt[4];
                ldsm4t(bt, vBase + (colByte >> 7) * 8192 + sw128(vrow * 128 + (colByte & 127)));
                mma16816(accO[2 * pr],     af, bt[0], bt[1]);
                mma16816(accO[2 * pr + 1], af, bt[2], bt[3]);
            }
        }
        __syncthreads();
        if (kt + 2 <= 15) LOAD_V(kt + 2, buf);
    }

    // ---- rowsum reduction ----
#pragma unroll
    for (int e = 0; e < 2; e++) {
        rs[e] += __shfl_xor_sync(0xffffffffu, rs[e], 1);
        rs[e] += __shfl_xor_sync(0xffffffffu, rs[e], 2);
    }
    if ((lane & 3) == 0) {
#pragma unroll
        for (int e = 0; e < 2; e++)
            sRS[wn * 64 + wm * 16 + (lane >> 2) + 8 * e] = rs[e];
    }
    __syncthreads();

    // ---- normalize + write g_Acat rows ----
    const int b = bh >> 4, h = bh & 15;
#pragma unroll
    for (int half = 0; half < 2; half++) {
        const int row = wm * 16 + (lane >> 2) + 8 * half;
        const float inv = 1.0f / (sRS[row] + sRS[64 + row]);
        const int m = b * 1024 + (n0 + row);
        __half* ReRow = g_Acat + (size_t)m * K_EFF;
        __half* ImRow = g_Acat + (size_t)(m + 4096) * K_EFF;
#pragma unroll
        for (int nt = 0; nt < 8; nt++) {
            const int col = wn * 64 + nt * 8 + (lane & 3) * 2;
            const int d = col & 63;
            const int c = h * 64 + d;
            const float v0 = accO[nt][half * 2] * inv;
            const float v1 = accO[nt][half * 2 + 1] * inv;
            const __half2 hp = __floats2half2_rn(v0, v1);
            if (col < 64) {
                *(uint32_t*)(ReRow + c) = *(const uint32_t*)&hp;
                *(uint32_t*)(ImRow + 1024 + c) = *(const uint32_t*)&hp;
            } else {
                const __half2 hn = __hneg2(hp);
                *(uint32_t*)(ReRow + 1024 + c) = *(const uint32_t*)&hn;
                *(uint32_t*)(ImRow + c) = *(const uint32_t*)&hp;
            }
        }
    }
}

// =================== launcher ===================
extern "C" void kernel_launch(void* const* d_in, const int* in_sizes, int n_in,
                              void* d_out, int out_size)
{
    const float* xr = (const float*)d_in[0];
    const float* xi = (const float*)d_in[1];
    const float* Wr = (const float*)d_in[2];
    const float* Wi = (const float*)d_in[3];
    const float* br = (const float*)d_in[4];
    const float* bi = (const float*)d_in[5];

    float* outR = (float*)d_out;
    float* outI = outR + (size_t)BATCH * SEQ * DIMV;

    cudaFuncSetAttribute(mma_gemm, cudaFuncAttributeMaxDynamicSharedMemorySize, SMEM_GEMM);
    cudaFuncSetAttribute(attn2_kernel, cudaFuncAttributeMaxDynamicSharedMemorySize, ATTN2_SMEM);

    // build fp16 A and W operands (merged)
    conv_aw_kernel<<<8192, 256>>>(xr, xi, Wr, Wi);

    // fused QKV projection; epilogue emits Qpack/Kpack/Vp16 fp16 directly
    mma_gemm<<<dim3(3072 / BN, 8192 / BM), 256, SMEM_GEMM>>>(br, bi, nullptr, nullptr, 0);

    // tensor-core attention (256 threads, 64q tiles, 2 CTAs/SM)
    attn2_kernel<<<dim3(SEQ / 64, BH), 256, ATTN2_SMEM>>>();

    // output projection -> d_out
    mma_gemm<<<dim3(1024 / BN, 8192 / BM), 256, SMEM_GEMM>>>(br + 3 * DIMV, bi + 3 * DIMV,
                                                             outR, outI, 1);
}

// round 15
// speedup vs baseline: 1.1253x; 1.0026x over previous
#include <cuda_runtime.h>
#include <cuda_fp16.h>
#include <math.h>
#include <stdint.h>

#define DIMV   1024
#define HEADS  16
#define DH     64
#define BATCH  4
#define SEQ    1024
#define BH     (BATCH*HEADS)
#define K_EFF  2048
#define KBYTES (K_EFF*2)

// ---------------- device scratch ----------------
__device__ __half g_Acat[(size_t)8192*K_EFF];        // [real rows 0..4095 | imag rows 4096..8191]
__device__ __half g_Wcat[(size_t)4096*K_EFF];        // 4 layers x 1024 rows: [Wr Wi]
__device__ __half g_Qpack[(size_t)BH*SEQ*128];       // [bh][n][qr | -qi]
__device__ __half g_Kpack[(size_t)BH*SEQ*128];       // [bh][n][kr | -ki]
__device__ __half g_Vp16[(size_t)BH*SEQ*128];        // [bh][n][vr | vi]

// ---------------- ptx helpers ----------------
__device__ __forceinline__ uint32_t smem_u32(const void* p) {
    uint32_t a;
    asm("{ .reg .u64 t; cvta.to.shared.u64 t, %1; cvt.u32.u64 %0, t; }" : "=r"(a) : "l"(p));
    return a;
}
__device__ __forceinline__ void cp16(uint32_t dst, const void* src) {
    asm volatile("cp.async.cg.shared.global [%0], [%1], 16;" :: "r"(dst), "l"(src) : "memory");
}
__device__ __forceinline__ void cp_commit() { asm volatile("cp.async.commit_group;" ::: "memory"); }
template<int N> __device__ __forceinline__ void cp_wait() {
    asm volatile("cp.async.wait_group %0;" :: "n"(N) : "memory");
}
__device__ __forceinline__ void ldsm4(uint32_t* r, uint32_t addr) {
    asm volatile("ldmatrix.sync.aligned.m8n8.x4.shared.b16 {%0,%1,%2,%3}, [%4];"
                 : "=r"(r[0]), "=r"(r[1]), "=r"(r[2]), "=r"(r[3]) : "r"(addr));
}
__device__ __forceinline__ void ldsm4t(uint32_t* r, uint32_t addr) {
    asm volatile("ldmatrix.sync.aligned.m8n8.x4.trans.shared.b16 {%0,%1,%2,%3}, [%4];"
                 : "=r"(r[0]), "=r"(r[1]), "=r"(r[2]), "=r"(r[3]) : "r"(addr));
}
__device__ __forceinline__ void mma16816(float* c, const uint32_t* a, uint32_t b0, uint32_t b1) {
    asm volatile(
        "mma.sync.aligned.m16n8k16.row.col.f32.f16.f16.f32 "
        "{%0,%1,%2,%3}, {%4,%5,%6,%7}, {%8,%9}, {%0,%1,%2,%3};"
        : "+f"(c[0]), "+f"(c[1]), "+f"(c[2]), "+f"(c[3])
        : "r"(a[0]), "r"(a[1]), "r"(a[2]), "r"(a[3]), "r"(b0), "r"(b1));
}
__device__ __forceinline__ uint32_t sw128(uint32_t off) { return off ^ ((off >> 3) & 0x70); }
__device__ __forceinline__ uint32_t hneg2u(uint32_t x) { return x ^ 0x80008000u; }

// ---------------- fp16 store helpers ----------------
__device__ __forceinline__ void st4h(__half* p, const float* v) {
    __half2 a = __floats2half2_rn(v[0], v[1]);
    __half2 b = __floats2half2_rn(v[2], v[3]);
    uint2 u;
    u.x = *(const uint32_t*)&a;
    u.y = *(const uint32_t*)&b;
    *(uint2*)p = u;
}
__device__ __forceinline__ void st4hn(__half* p, const float* v) {
    __half2 a = __floats2half2_rn(-v[0], -v[1]);
    __half2 b = __floats2half2_rn(-v[2], -v[3]);
    uint2 u;
    u.x = *(const uint32_t*)&a;
    u.y = *(const uint32_t*)&b;
    *(uint2*)p = u;
}

// ---------------- merged conversion: A + W operands ----------------
__global__ void conv_aw_kernel(const float* __restrict__ ar, const float* __restrict__ ai,
                               const float* __restrict__ Wr, const float* __restrict__ Wi)
{
    if (blockIdx.x < 4096) {
        const int idx = blockIdx.x * 256 + threadIdx.x;
        const int row = idx >> 8;
        const int c = (idx & 255) << 2;
        const size_t src = (size_t)row * 1024 + c;
        const float4 vr = *(const float4*)(ar + src);
        const float4 vi = *(const float4*)(ai + src);
        const float fr[4] = {vr.x, vr.y, vr.z, vr.w};
        const float fi[4] = {vi.x, vi.y, vi.z, vi.w};
        __half* Re = g_Acat + (size_t)row * K_EFF + c;
        __half* Im = g_Acat + (size_t)(row + 4096) * K_EFF + c;
        st4h (Re + 0,    fr);
        st4hn(Re + 1024, fi);
        st4h (Im + 0,    fi);
        st4h (Im + 1024, fr);
    } else {
        const int idx = (blockIdx.x - 4096) * 256 + threadIdx.x;
        const int row = idx >> 8;
        const int c = (idx & 255) << 2;
        const size_t src = (size_t)row * 1024 + c;
        const float4 vr = *(const float4*)(Wr + src);
        const float4 vi = *(const float4*)(Wi + src);
        const float fr[4] = {vr.x, vr.y, vr.z, vr.w};
        const float fi[4] = {vi.x, vi.y, vi.z, vi.w};
        __half* W = g_Wcat + (size_t)row * K_EFF + c;
        st4h(W + 0,    fr);
        st4h(W + 1024, fi);
    }
}

// ---------------- mma.sync projection GEMM (R11 form — FROZEN) ----------------
#define BM 128
#define BN 128
#define BK 64
#define NITER (K_EFF/BK)     // 32
#define A_ST  16384
#define ST_SZ 32768
#define SMEM_GEMM (3*ST_SZ)

__device__ __forceinline__ void load_stage(uint32_t sbase, int s, int kt, int tid,
                                           const __half* Ab, const __half* Bb)
{
    const char* aSrc = (const char*)Ab + (size_t)kt * (BK * 2);
    const char* bSrc = (const char*)Bb + (size_t)kt * (BK * 2);
    const uint32_t aDst = sbase + s * ST_SZ;
    const uint32_t bDst = aDst + A_ST;
#pragma unroll
    for (int i = 0; i < 4; i++) {
        const int q = tid + i * 256;
        const int row = q >> 3, cc = q & 7;
        const uint32_t sw = sw128(row * 128 + cc * 16);
        cp16(aDst + sw, aSrc + (size_t)row * KBYTES + cc * 16);
        cp16(bDst + sw, bSrc + (size_t)row * KBYTES + cc * 16);
    }
}

// epilogue: mode 0 writes Qpack/Kpack/Vp16 fp16; mode 1 writes final fp32 planes
__device__ __forceinline__ void epi_store(int mode, int gm, int gc,
                                          float v0, float v1,
                                          const float* biasR, const float* biasI,
                                          float* outR, float* outI)
{
    const int plane = gm >> 12;
    const int m = gm & 4095;
    const int b = m >> 10, n = m & 1023;
    const float* bias = plane ? biasI : biasR;
    const float f0 = v0 + bias[gc];
    const float f1 = v1 + bias[gc + 1];
    if (mode == 0) {
        const int layer = gc >> 10;
        const int cw = gc & 1023;
        const int h = cw >> 6, d = cw & 63;
        const int bh = b * HEADS + h;
        const __half2 hp = __floats2half2_rn(f0, f1);
        if (layer == 2) {
            __half* dst = g_Vp16 + ((size_t)bh * SEQ + n) * 128 + plane * 64 + d;
            *(uint32_t*)dst = *(const uint32_t*)&hp;
        } else {
            const __half2 hs = plane ? __hneg2(hp) : hp;
            __half* base = (layer == 0) ? g_Qpack : g_Kpack;
            __half* dst = base + ((size_t)bh * SEQ + n) * 128 + plane * 64 + d;
            *(uint32_t*)dst = *(const uint32_t*)&hs;
        }
    } else {
        float* base = plane ? outI : outR;
        float2 v; v.x = f0; v.y = f1;
        *(float2*)(base + (size_t)m * 1024 + gc) = v;
    }
}

__global__ void __launch_bounds__(256, 2) mma_gemm(
    const float* __restrict__ biasR, const float* __restrict__ biasI,
    float* __restrict__ outR, float* __restrict__ outI, int mode)
{
    extern __shared__ char smem[];
    const uint32_t sbase = smem_u32(smem);
    const int tid = threadIdx.x;
    const int lane = tid & 31;
    const int wid = tid >> 5;
    const int wm = wid & 3;
    const int wn = wid >> 2;

    const __half* Ab = g_Acat + (size_t)blockIdx.y * BM * K_EFF;
    const __half* Bb = g_Wcat + (mode ? (size_t)3072 * K_EFF : 0)
                              + (size_t)blockIdx.x * BN * K_EFF;

    float acc[2][8][4];
#pragma unroll
    for (int mt = 0; mt < 2; mt++)
#pragma unroll
        for (int nt = 0; nt < 8; nt++)
#pragma unroll
            for (int r = 0; r < 4; r++) acc[mt][nt][r] = 0.f;

    load_stage(sbase, 0, 0, tid, Ab, Bb); cp_commit();
    load_stage(sbase, 1, 1, tid, Ab, Bb); cp_commit();

    const int lr_ = lane & 15;
    const int lc16 = (lane >> 4) * 16;

    for (int kt = 0; kt < NITER; kt++) {
        cp_wait<1>();
        __syncthreads();
        const int slot = kt % 3;
        const uint32_t aB = sbase + slot * ST_SZ;
        const uint32_t bB = aB + A_ST;
#pragma unroll
        for (int ks = 0; ks < 4; ks++) {
            const uint32_t cb = ks * 32 + lc16;
            uint32_t af[2][4], bf[4][4];
#pragma unroll
            for (int mt = 0; mt < 2; mt++) {
                const uint32_t off = (uint32_t)(wm * 32 + mt * 16 + lr_) * 128 + cb;
                ldsm4(af[mt], aB + sw128(off));
            }
#pragma unroll
            for (int pr = 0; pr < 4; pr++) {
                const uint32_t off = (uint32_t)(wn * 64 + pr * 16 + lr_) * 128 + cb;
                ldsm4(bf[pr], bB + sw128(off));
            }
#pragma unroll
            for (int mt = 0; mt < 2; mt++)
#pragma unroll
                for (int nt = 0; nt < 8; nt++)
                    mma16816(acc[mt][nt], af[mt],
                             bf[nt >> 1][nt & 1], bf[nt >> 1][(nt & 1) + 2]);
        }
        const int pk = kt + 2;
        if (pk < NITER) load_stage(sbase, pk % 3, pk, tid, Ab, Bb);
        cp_commit();
    }

    const int blockRow = blockIdx.y * BM;
    const int blockCol = blockIdx.x * BN;
#pragma unroll
    for (int mt = 0; mt < 2; mt++) {
        const int gr0 = blockRow + wm * 32 + mt * 16 + (lane >> 2);
#pragma unroll
        for (int nt = 0; nt < 8; nt++) {
            const int gc = blockCol + wn * 64 + nt * 8 + (lane & 3) * 2;
            epi_store(mode, gr0,     gc, acc[mt][nt][0], acc[mt][nt][1], biasR, biasI, outR, outI);
            epi_store(mode, gr0 + 8, gc, acc[mt][nt][2], acc[mt][nt][3], biasR, biasI, outR, outI);
        }
    }
}

// =================== tensor-core attention (fp16, 256 thr / 64q, 2 CTAs/SM, 3 syncs/kt) ===================
// smem: Q 16KB | K 2x16KB | V 2x16KB | P 8KB | rowsum 512B  (~88.5KB -> 2 CTAs/SM)
#define SQ_OFF 0
#define SK_OFF 16384
#define SV_OFF (SK_OFF + 2*16384)
#define SP_OFF (SV_OFF + 2*16384)
#define SRS_OFF (SP_OFF + 8192)
#define ATTN2_SMEM (SRS_OFF + 512)

__global__ void __launch_bounds__(256, 2) attn2_kernel()
{
    extern __shared__ char sm[];
    const uint32_t sb = smem_u32(sm);
    const uint32_t sQ = sb + SQ_OFF;
    const uint32_t sK = sb + SK_OFF;
    const uint32_t sV = sb + SV_OFF;
    const uint32_t sP = sb + SP_OFF;
    float* sRS = (float*)(sm + SRS_OFF);

    const int tid = threadIdx.x;
    const int lane = tid & 31;
    const int wid = tid >> 5;     // 0..7
    const int wm = wid & 3;       // 16-query row group
    const int wn = wid >> 2;      // 0/1: key half (S) / dh-col half (PV)
    const int bh = blockIdx.y;
    const int n0 = blockIdx.x * 64;

    const char* Qg = (const char*)(g_Qpack + ((size_t)bh * SEQ + n0) * 128);
    const char* Kg = (const char*)(g_Kpack + (size_t)bh * SEQ * 128);
    const char* Vg = (const char*)(g_Vp16 + (size_t)bh * SEQ * 128);

    // Q: 64 rows x 256B (two 8KB chunks)
#pragma unroll
    for (int i = 0; i < 4; i++) {
        const int q = tid + i * 256;
        const int row = q >> 4, cc = q & 15;
        const int ch = cc >> 3, w = cc & 7;
        cp16(sQ + ch * 8192 + sw128(row * 128 + w * 16),
             Qg + (size_t)row * 256 + cc * 16);
    }
    cp_commit();

#define LOAD_K(ktile, buf) do { \
    _Pragma("unroll") \
    for (int i = 0; i < 4; i++) { \
        const int q = tid + i * 256; \
        const int row = q >> 4, cc = q & 15; \
        const int ch = cc >> 3, w = cc & 7; \
        cp16(sK + (buf) * 16384 + ch * 8192 + sw128(row * 128 + w * 16), \
             Kg + (size_t)((ktile) * 64 + row) * 256 + cc * 16); \
    } \
    cp_commit(); } while (0)

#define LOAD_V(ktile, buf) do { \
    _Pragma("unroll") \
    for (int i = 0; i < 4; i++) { \
        const int q = tid + i * 256; \
        const int row = q >> 4, cc = q & 15; \
        const int ch = cc >> 3, w = cc & 7; \
        cp16(sV + (buf) * 16384 + ch * 8192 + sw128(row * 128 + w * 16), \
             Vg + (size_t)((ktile) * 64 + row) * 256 + cc * 16); \
    } \
    cp_commit(); } while (0)

    LOAD_K(0, 0);
    LOAD_V(0, 0);
    LOAD_K(1, 1);
    LOAD_V(1, 1);

    float accO[8][4];
#pragma unroll
    for (int nt = 0; nt < 8; nt++)
#pragma unroll
        for (int e = 0; e < 4; e++) accO[nt][e] = 0.f;
    float rs[2] = {0.f, 0.f};

    const int lr_ = lane & 15;
    const int lc16 = (lane >> 4) * 16;
    const int lr8 = lane & 7;
    const int lgrp = lane >> 3;

    for (int kt = 0; kt < 16; kt++) {
        const int buf = kt & 1;
        // ---- barrier 1: K(kt) ready ----
        if (kt <= 14) cp_wait<3>(); else cp_wait<1>();
        __syncthreads();

        float accR[4][4], accI[4][4];
#pragma unroll
        for (int nt = 0; nt < 4; nt++)
#pragma unroll
            for (int e = 0; e < 4; e++) { accR[nt][e] = 0.f; accI[nt][e] = 0.f; }

        const uint32_t kBase = sK + buf * 16384;
#pragma unroll
        for (int dks = 0; dks < 4; dks++) {
            const uint32_t w = dks * 32 + lc16;
            uint32_t qf0[4], qf1[4], qneg[4];
            const uint32_t qoff = sw128((uint32_t)(wm * 16 + lr_) * 128 + w);
            ldsm4(qf0, sQ + qoff);                   // qr slice
            ldsm4(qf1, sQ + 8192 + qoff);            // -qi slice
#pragma unroll
            for (int e = 0; e < 4; e++) qneg[e] = hneg2u(qf1[e]);

            uint32_t b0[2][4], b1[2][4];
#pragma unroll
            for (int pr = 0; pr < 2; pr++) {
                const uint32_t koff = sw128((uint32_t)(wn * 32 + pr * 16 + lr_) * 128 + w);
                ldsm4(b0[pr], kBase + koff);
                ldsm4(b1[pr], kBase + 8192 + koff);
            }
#pragma unroll
            for (int nt = 0; nt < 4; nt++) {
                const uint32_t br0 = b0[nt >> 1][nt & 1], br1 = b0[nt >> 1][(nt & 1) + 2];
                const uint32_t bi0 = b1[nt >> 1][nt & 1], bi1 = b1[nt >> 1][(nt & 1) + 2];
                mma16816(accR[nt], qf0,  br0, br1);
                mma16816(accR[nt], qf1,  bi0, bi1);
                mma16816(accI[nt], qneg, br0, br1);
                mma16816(accI[nt], qf0,  bi0, bi1);
            }
        }

        // ---- softmax -> P (fp16); inputs are registers, no barrier needed ----
#pragma unroll
        for (int nt = 0; nt < 4; nt++) {
            float p[4];
#pragma unroll
            for (int e = 0; e < 4; e++) {
                const float srv = accR[nt][e];
                const float siv = accI[nt][e];
                p[e] = __expf(sqrtf(srv * srv + siv * siv) * 0.125f);
            }
            rs[0] += p[0] + p[1];
            rs[1] += p[2] + p[3];
            const int keyb = (wn * 32 + nt * 8 + (lane & 3) * 2) * 2;
            const int row0 = wm * 16 + (lane >> 2);
#pragma unroll
            for (int half = 0; half < 2; half++) {
                const __half2 hp = __floats2half2_rn(p[half * 2], p[half * 2 + 1]);
                const uint32_t off = (uint32_t)(row0 + half * 8) * 128 + keyb;
                *(uint32_t*)(sm + SP_OFF + sw128(off)) = *(const uint32_t*)&hp;
            }
        }

        // ---- barrier 2 (merged): V(kt) ready + P visible + K-slot drained ----
        if (kt <= 14) cp_wait<2>(); else cp_wait<0>();
        __syncthreads();
        if (kt + 2 <= 15) LOAD_K(kt + 2, buf);

        // ---- PV ----
        const uint32_t vBase = sV + buf * 16384;
#pragma unroll
        for (int ks = 0; ks < 4; ks++) {
            const uint32_t cb = ks * 32 + lc16;
            uint32_t af[4];
            {
                const uint32_t off = (uint32_t)(wm * 16 + lr_) * 128 + cb;
                ldsm4(af, sP + sw128(off));
            }
#pragma unroll
            for (int pr = 0; pr < 4; pr++) {
                const uint32_t colByte = (uint32_t)(wn * 128 + pr * 32 + ((lgrp >> 1) << 4));
                const uint32_t vrow = (uint32_t)(ks * 16 + ((lgrp & 1) << 3) + lr8);
                uint32_t bt[4];
                ldsm4t(bt, vBase + (colByte >> 7) * 8192 + sw128(vrow * 128 + (colByte & 127)));
                mma16816(accO[2 * pr],     af, bt[0], bt[1]);
                mma16816(accO[2 * pr + 1], af, bt[2], bt[3]);
            }
        }
        // ---- barrier 3: V-slot drained ----
        __syncthreads();
        if (kt + 2 <= 15) LOAD_V(kt + 2, buf);
    }

    // ---- rowsum reduction ----
#pragma unroll
    for (int e = 0; e < 2; e++) {
        rs[e] += __shfl_xor_sync(0xffffffffu, rs[e], 1);
        rs[e] += __shfl_xor_sync(0xffffffffu, rs[e], 2);
    }
    if ((lane & 3) == 0) {
#pragma unroll
        for (int e = 0; e < 2; e++)
            sRS[wn * 64 + wm * 16 + (lane >> 2) + 8 * e] = rs[e];
    }
    __syncthreads();

    // ---- normalize + write g_Acat rows ----
    const int b = bh >> 4, h = bh & 15;
#pragma unroll
    for (int half = 0; half < 2; half++) {
        const int row = wm * 16 + (lane >> 2) + 8 * half;
        const float inv = 1.0f / (sRS[row] + sRS[64 + row]);
        const int m = b * 1024 + (n0 + row);
        __half* ReRow = g_Acat + (size_t)m * K_EFF;
        __half* ImRow = g_Acat + (size_t)(m + 4096) * K_EFF;
#pragma unroll
        for (int nt = 0; nt < 8; nt++) {
            const int col = wn * 64 + nt * 8 + (lane & 3) * 2;
            const int d = col & 63;
            const int c = h * 64 + d;
            const float v0 = accO[nt][half * 2] * inv;
            const float v1 = accO[nt][half * 2 + 1] * inv;
            const __half2 hp = __floats2half2_rn(v0, v1);
            if (col < 64) {
                *(uint32_t*)(ReRow + c) = *(const uint32_t*)&hp;
                *(uint32_t*)(ImRow + 1024 + c) = *(const uint32_t*)&hp;
            } else {
                const __half2 hn = __hneg2(hp);
                *(uint32_t*)(ReRow + 1024 + c) = *(const uint32_t*)&hn;
                *(uint32_t*)(ImRow + c) = *(const uint32_t*)&hp;
            }
        }
    }
}

// =================== launcher ===================
extern "C" void kernel_launch(void* const* d_in, const int* in_sizes, int n_in,
                              void* d_out, int out_size)
{
    const float* xr = (const float*)d_in[0];
    const float* xi = (const float*)d_in[1];
    const float* Wr = (const float*)d_in[2];
    const float* Wi = (const float*)d_in[3];
    const float* br = (const float*)d_in[4];
    const float* bi = (const float*)d_in[5];

    float* outR = (float*)d_out;
    float* outI = outR + (size_t)BATCH * SEQ * DIMV;

    cudaFuncSetAttribute(mma_gemm, cudaFuncAttributeMaxDynamicSharedMemorySize, SMEM_GEMM);
    cudaFuncSetAttribute(attn2_kernel, cudaFuncAttributeMaxDynamicSharedMemorySize, ATTN2_SMEM);

    // build fp16 A and W operands (merged)
    conv_aw_kernel<<<8192, 256>>>(xr, xi, Wr, Wi);

    // fused QKV projection; epilogue emits Qpack/Kpack/Vp16 fp16 directly
    mma_gemm<<<dim3(3072 / BN, 8192 / BM), 256, SMEM_GEMM>>>(br, bi, nullptr, nullptr, 0);

    // tensor-core attention (256 threads, 64q tiles, 2 CTAs/SM, 3 syncs/kt)
    attn2_kernel<<<dim3(SEQ / 64, BH), 256, ATTN2_SMEM>>>();

    // output projection -> d_out
    mma_gemm<<<dim3(1024 / BN, 8192 / BM), 256, SMEM_GEMM>>>(br + 3 * DIMV, bi + 3 * DIMV,
                                                             outR, outI, 1);
}

// round 16
// speedup vs baseline: 1.1956x; 1.0625x over previous
#include <cuda_runtime.h>
#include <cuda_fp16.h>
#include <math.h>
#include <stdint.h>

#define DIMV   1024
#define HEADS  16
#define DH     64
#define BATCH  4
#define SEQ    1024
#define BH     (BATCH*HEADS)
#define K_EFF  2048
#define KBYTES (K_EFF*2)

// ---------------- device scratch ----------------
__device__ __half g_Acat[(size_t)8192*K_EFF];
__device__ __half g_Wcat[(size_t)4096*K_EFF];
__device__ __half g_Qpack[(size_t)BH*SEQ*128];
__device__ __half g_Kpack[(size_t)BH*SEQ*128];
__device__ __half g_Vp16[(size_t)BH*SEQ*128];
__device__ int    g_cnt[128];   // [0..95]: b*24+layer*8+colblk (target 16); [96..99]: attn per-batch (target 256)

// ---------------- ptx helpers ----------------
__device__ __forceinline__ uint32_t smem_u32(const void* p) {
    uint32_t a;
    asm("{ .reg .u64 t; cvta.to.shared.u64 t, %1; cvt.u32.u64 %0, t; }" : "=r"(a) : "l"(p));
    return a;
}
__device__ __forceinline__ void cp16(uint32_t dst, const void* src) {
    asm volatile("cp.async.cg.shared.global [%0], [%1], 16;" :: "r"(dst), "l"(src) : "memory");
}
__device__ __forceinline__ void cp_commit() { asm volatile("cp.async.commit_group;" ::: "memory"); }
template<int N> __device__ __forceinline__ void cp_wait() {
    asm volatile("cp.async.wait_group %0;" :: "n"(N) : "memory");
}
__device__ __forceinline__ void ldsm4(uint32_t* r, uint32_t addr) {
    asm volatile("ldmatrix.sync.aligned.m8n8.x4.shared.b16 {%0,%1,%2,%3}, [%4];"
                 : "=r"(r[0]), "=r"(r[1]), "=r"(r[2]), "=r"(r[3]) : "r"(addr));
}
__device__ __forceinline__ void ldsm4t(uint32_t* r, uint32_t addr) {
    asm volatile("ldmatrix.sync.aligned.m8n8.x4.trans.shared.b16 {%0,%1,%2,%3}, [%4];"
                 : "=r"(r[0]), "=r"(r[1]), "=r"(r[2]), "=r"(r[3]) : "r"(addr));
}
__device__ __forceinline__ void mma16816(float* c, const uint32_t* a, uint32_t b0, uint32_t b1) {
    asm volatile(
        "mma.sync.aligned.m16n8k16.row.col.f32.f16.f16.f32 "
        "{%0,%1,%2,%3}, {%4,%5,%6,%7}, {%8,%9}, {%0,%1,%2,%3};"
        : "+f"(c[0]), "+f"(c[1]), "+f"(c[2]), "+f"(c[3])
        : "r"(a[0]), "r"(a[1]), "r"(a[2]), "r"(a[3]), "r"(b0), "r"(b1));
}
__device__ __forceinline__ uint32_t sw128(uint32_t off) { return off ^ ((off >> 3) & 0x70); }
__device__ __forceinline__ uint32_t hneg2u(uint32_t x) { return x ^ 0x80008000u; }

// ---------------- fp16 store helpers ----------------
__device__ __forceinline__ void st4h(__half* p, const float* v) {
    __half2 a = __floats2half2_rn(v[0], v[1]);
    __half2 b = __floats2half2_rn(v[2], v[3]);
    uint2 u;
    u.x = *(const uint32_t*)&a;
    u.y = *(const uint32_t*)&b;
    *(uint2*)p = u;
}
__device__ __forceinline__ void st4hn(__half* p, const float* v) {
    __half2 a = __floats2half2_rn(-v[0], -v[1]);
    __half2 b = __floats2half2_rn(-v[2], -v[3]);
    uint2 u;
    u.x = *(const uint32_t*)&a;
    u.y = *(const uint32_t*)&b;
    *(uint2*)p = u;
}

// ---------------- merged conversion: A + W operands (+ counter reset) ----------------
__global__ void conv_aw_kernel(const float* __restrict__ ar, const float* __restrict__ ai,
                               const float* __restrict__ Wr, const float* __restrict__ Wi)
{
    if (blockIdx.x == 0 && threadIdx.x < 128) g_cnt[threadIdx.x] = 0;
    if (blockIdx.x < 4096) {
        const int idx = blockIdx.x * 256 + threadIdx.x;
        const int row = idx >> 8;
        const int c = (idx & 255) << 2;
        const size_t src = (size_t)row * 1024 + c;
        const float4 vr = *(const float4*)(ar + src);
        const float4 vi = *(const float4*)(ai + src);
        const float fr[4] = {vr.x, vr.y, vr.z, vr.w};
        const float fi[4] = {vi.x, vi.y, vi.z, vi.w};
        __half* Re = g_Acat + (size_t)row * K_EFF + c;
        __half* Im = g_Acat + (size_t)(row + 4096) * K_EFF + c;
        st4h (Re + 0,    fr);
        st4hn(Re + 1024, fi);
        st4h (Im + 0,    fi);
        st4h (Im + 1024, fr);
    } else {
        const int idx = (blockIdx.x - 4096) * 256 + threadIdx.x;
        const int row = idx >> 8;
        const int c = (idx & 255) << 2;
        const size_t src = (size_t)row * 1024 + c;
        const float4 vr = *(const float4*)(Wr + src);
        const float4 vi = *(const float4*)(Wi + src);
        const float fr[4] = {vr.x, vr.y, vr.z, vr.w};
        const float fi[4] = {vi.x, vi.y, vi.z, vi.w};
        __half* W = g_Wcat + (size_t)row * K_EFF + c;
        st4h(W + 0,    fr);
        st4h(W + 1024, fi);
    }
}

// ---------------- GEMM body (R11 form, frozen math) ----------------
#define BM 128
#define BN 128
#define BK 64
#define NITER (K_EFF/BK)
#define A_ST  16384
#define ST_SZ 32768
#define SMEM_GEMM (3*ST_SZ)

__device__ __forceinline__ void load_stage(uint32_t sbase, int s, int kt, int tid,
                                           const __half* Ab, const __half* Bb)
{
    const char* aSrc = (const char*)Ab + (size_t)kt * (BK * 2);
    const char* bSrc = (const char*)Bb + (size_t)kt * (BK * 2);
    const uint32_t aDst = sbase + s * ST_SZ;
    const uint32_t bDst = aDst + A_ST;
#pragma unroll
    for (int i = 0; i < 4; i++) {
        const int q = tid + i * 256;
        const int row = q >> 3, cc = q & 7;
        const uint32_t sw = sw128(row * 128 + cc * 16);
        cp16(aDst + sw, aSrc + (size_t)row * KBYTES + cc * 16);
        cp16(bDst + sw, bSrc + (size_t)row * KBYTES + cc * 16);
    }
}

__device__ __forceinline__ void epi_store(int mode, int gm, int gc,
                                          float v0, float v1,
                                          const float* biasR, const float* biasI,
                                          float* outR, float* outI)
{
    const int plane = gm >> 12;
    const int m = gm & 4095;
    const int b = m >> 10, n = m & 1023;
    const float* bias = plane ? biasI : biasR;
    const float f0 = v0 + bias[gc];
    const float f1 = v1 + bias[gc + 1];
    if (mode == 0) {
        const int layer = gc >> 10;
        const int cw = gc & 1023;
        const int h = cw >> 6, d = cw & 63;
        const int bh = b * HEADS + h;
        const __half2 hp = __floats2half2_rn(f0, f1);
        if (layer == 2) {
            __half* dst = g_Vp16 + ((size_t)bh * SEQ + n) * 128 + plane * 64 + d;
            *(uint32_t*)dst = *(const uint32_t*)&hp;
        } else {
            const __half2 hs = plane ? __hneg2(hp) : hp;
            __half* base = (layer == 0) ? g_Qpack : g_Kpack;
            __half* dst = base + ((size_t)bh * SEQ + n) * 128 + plane * 64 + d;
            *(uint32_t*)dst = *(const uint32_t*)&hs;
        }
    } else {
        float* base = plane ? outI : outR;
        float2 v; v.x = f0; v.y = f1;
        *(float2*)(base + (size_t)m * 1024 + gc) = v;
    }
}

__device__ __forceinline__ void gemm_body(char* smem, int mode, int bxi, int byi,
                                          const float* biasR, const float* biasI,
                                          float* outR, float* outI)
{
    const uint32_t sbase = smem_u32(smem);
    const int tid = threadIdx.x;
    const int lane = tid & 31;
    const int wid = tid >> 5;
    const int wm = wid & 3;
    const int wn = wid >> 2;

    const __half* Ab = g_Acat + (size_t)byi * BM * K_EFF;
    const __half* Bb = g_Wcat + (mode ? (size_t)3072 * K_EFF : 0)
                              + (size_t)bxi * BN * K_EFF;

    float acc[2][8][4];
#pragma unroll
    for (int mt = 0; mt < 2; mt++)
#pragma unroll
        for (int nt = 0; nt < 8; nt++)
#pragma unroll
            for (int r = 0; r < 4; r++) acc[mt][nt][r] = 0.f;

    load_stage(sbase, 0, 0, tid, Ab, Bb); cp_commit();
    load_stage(sbase, 1, 1, tid, Ab, Bb); cp_commit();

    const int lr_ = lane & 15;
    const int lc16 = (lane >> 4) * 16;

    for (int kt = 0; kt < NITER; kt++) {
        cp_wait<1>();
        __syncthreads();
        const int slot = kt % 3;
        const uint32_t aB = sbase + slot * ST_SZ;
        const uint32_t bB = aB + A_ST;
#pragma unroll
        for (int ks = 0; ks < 4; ks++) {
            const uint32_t cb = ks * 32 + lc16;
            uint32_t af[2][4], bf[4][4];
#pragma unroll
            for (int mt = 0; mt < 2; mt++) {
                const uint32_t off = (uint32_t)(wm * 32 + mt * 16 + lr_) * 128 + cb;
                ldsm4(af[mt], aB + sw128(off));
            }
#pragma unroll
            for (int pr = 0; pr < 4; pr++) {
                const uint32_t off = (uint32_t)(wn * 64 + pr * 16 + lr_) * 128 + cb;
                ldsm4(bf[pr], bB + sw128(off));
            }
#pragma unroll
            for (int mt = 0; mt < 2; mt++)
#pragma unroll
                for (int nt = 0; nt < 8; nt++)
                    mma16816(acc[mt][nt], af[mt],
                             bf[nt >> 1][nt & 1], bf[nt >> 1][(nt & 1) + 2]);
        }
        const int pk = kt + 2;
        if (pk < NITER) load_stage(sbase, pk % 3, pk, tid, Ab, Bb);
        cp_commit();
    }

    const int blockRow = byi * BM;
    const int blockCol = bxi * BN;
#pragma unroll
    for (int mt = 0; mt < 2; mt++) {
        const int gr0 = blockRow + wm * 32 + mt * 16 + (lane >> 2);
#pragma unroll
        for (int nt = 0; nt < 8; nt++) {
            const int gc = blockCol + wn * 64 + nt * 8 + (lane & 3) * 2;
            epi_store(mode, gr0,     gc, acc[mt][nt][0], acc[mt][nt][1], biasR, biasI, outR, outI);
            epi_store(mode, gr0 + 8, gc, acc[mt][nt][2], acc[mt][nt][3], biasR, biasI, outR, outI);
        }
    }
}

// ---------------- attention body (R14 form, frozen math) ----------------
#define SQ_OFF 0
#define SK_OFF 16384
#define SV_OFF (SK_OFF + 2*16384)
#define SP_OFF (SV_OFF + 2*16384)
#define SRS_OFF (SP_OFF + 8192)

__device__ __forceinline__ void attn_body(char* sm, int bh, int n0)
{
    const uint32_t sb = smem_u32(sm);
    const uint32_t sQ = sb + SQ_OFF;
    const uint32_t sK = sb + SK_OFF;
    const uint32_t sV = sb + SV_OFF;
    const uint32_t sP = sb + SP_OFF;
    float* sRS = (float*)(sm + SRS_OFF);

    const int tid = threadIdx.x;
    const int lane = tid & 31;
    const int wid = tid >> 5;
    const int wm = wid & 3;
    const int wn = wid >> 2;

    const char* Qg = (const char*)(g_Qpack + ((size_t)bh * SEQ + n0) * 128);
    const char* Kg = (const char*)(g_Kpack + (size_t)bh * SEQ * 128);
    const char* Vg = (const char*)(g_Vp16 + (size_t)bh * SEQ * 128);

#pragma unroll
    for (int i = 0; i < 4; i++) {
        const int q = tid + i * 256;
        const int row = q >> 4, cc = q & 15;
        const int ch = cc >> 3, w = cc & 7;
        cp16(sQ + ch * 8192 + sw128(row * 128 + w * 16),
             Qg + (size_t)row * 256 + cc * 16);
    }
    cp_commit();

#define LOAD_K(ktile, buf) do { \
    _Pragma("unroll") \
    for (int i = 0; i < 4; i++) { \
        const int q = tid + i * 256; \
        const int row = q >> 4, cc = q & 15; \
        const int ch = cc >> 3, w = cc & 7; \
        cp16(sK + (buf) * 16384 + ch * 8192 + sw128(row * 128 + w * 16), \
             Kg + (size_t)((ktile) * 64 + row) * 256 + cc * 16); \
    } \
    cp_commit(); } while (0)

#define LOAD_V(ktile, buf) do { \
    _Pragma("unroll") \
    for (int i = 0; i < 4; i++) { \
        const int q = tid + i * 256; \
        const int row = q >> 4, cc = q & 15; \
        const int ch = cc >> 3, w = cc & 7; \
        cp16(sV + (buf) * 16384 + ch * 8192 + sw128(row * 128 + w * 16), \
             Vg + (size_t)((ktile) * 64 + row) * 256 + cc * 16); \
    } \
    cp_commit(); } while (0)

    LOAD_K(0, 0);
    LOAD_V(0, 0);
    LOAD_K(1, 1);
    LOAD_V(1, 1);

    float accO[8][4];
#pragma unroll
    for (int nt = 0; nt < 8; nt++)
#pragma unroll
        for (int e = 0; e < 4; e++) accO[nt][e] = 0.f;
    float rs[2] = {0.f, 0.f};

    const int lr_ = lane & 15;
    const int lc16 = (lane >> 4) * 16;
    const int lr8 = lane & 7;
    const int lgrp = lane >> 3;

    for (int kt = 0; kt < 16; kt++) {
        const int buf = kt & 1;
        if (kt <= 14) cp_wait<3>(); else cp_wait<1>();
        __syncthreads();

        float accR[4][4], accI[4][4];
#pragma unroll
        for (int nt = 0; nt < 4; nt++)
#pragma unroll
            for (int e = 0; e < 4; e++) { accR[nt][e] = 0.f; accI[nt][e] = 0.f; }

        const uint32_t kBase = sK + buf * 16384;
#pragma unroll
        for (int dks = 0; dks < 4; dks++) {
            const uint32_t w = dks * 32 + lc16;
            uint32_t qf0[4], qf1[4], qneg[4];
            const uint32_t qoff = sw128((uint32_t)(wm * 16 + lr_) * 128 + w);
            ldsm4(qf0, sQ + qoff);
            ldsm4(qf1, sQ + 8192 + qoff);
#pragma unroll
            for (int e = 0; e < 4; e++) qneg[e] = hneg2u(qf1[e]);

            uint32_t b0[2][4], b1[2][4];
#pragma unroll
            for (int pr = 0; pr < 2; pr++) {
                const uint32_t koff = sw128((uint32_t)(wn * 32 + pr * 16 + lr_) * 128 + w);
                ldsm4(b0[pr], kBase + koff);
                ldsm4(b1[pr], kBase + 8192 + koff);
            }
#pragma unroll
            for (int nt = 0; nt < 4; nt++) {
                const uint32_t br0 = b0[nt >> 1][nt & 1], br1 = b0[nt >> 1][(nt & 1) + 2];
                const uint32_t bi0 = b1[nt >> 1][nt & 1], bi1 = b1[nt >> 1][(nt & 1) + 2];
                mma16816(accR[nt], qf0,  br0, br1);
                mma16816(accR[nt], qf1,  bi0, bi1);
                mma16816(accI[nt], qneg, br0, br1);
                mma16816(accI[nt], qf0,  bi0, bi1);
            }
        }

#pragma unroll
        for (int nt = 0; nt < 4; nt++) {
            float p[4];
#pragma unroll
            for (int e = 0; e < 4; e++) {
                const float srv = accR[nt][e];
                const float siv = accI[nt][e];
                p[e] = __expf(sqrtf(srv * srv + siv * siv) * 0.125f);
            }
            rs[0] += p[0] + p[1];
            rs[1] += p[2] + p[3];
            const int keyb = (wn * 32 + nt * 8 + (lane & 3) * 2) * 2;
            const int row0 = wm * 16 + (lane >> 2);
#pragma unroll
            for (int half = 0; half < 2; half++) {
                const __half2 hp = __floats2half2_rn(p[half * 2], p[half * 2 + 1]);
                const uint32_t off = (uint32_t)(row0 + half * 8) * 128 + keyb;
                *(uint32_t*)(sm + SP_OFF + sw128(off)) = *(const uint32_t*)&hp;
            }
        }

        if (kt <= 14) cp_wait<2>(); else cp_wait<0>();
        __syncthreads();
        if (kt + 2 <= 15) LOAD_K(kt + 2, buf);

        const uint32_t vBase = sV + buf * 16384;
#pragma unroll
        for (int ks = 0; ks < 4; ks++) {
            const uint32_t cb = ks * 32 + lc16;
            uint32_t af[4];
            {
                const uint32_t off = (uint32_t)(wm * 16 + lr_) * 128 + cb;
                ldsm4(af, sP + sw128(off));
            }
#pragma unroll
            for (int pr = 0; pr < 4; pr++) {
                const uint32_t colByte = (uint32_t)(wn * 128 + pr * 32 + ((lgrp >> 1) << 4));
                const uint32_t vrow = (uint32_t)(ks * 16 + ((lgrp & 1) << 3) + lr8);
                uint32_t bt[4];
                ldsm4t(bt, vBase + (colByte >> 7) * 8192 + sw128(vrow * 128 + (colByte & 127)));
                mma16816(accO[2 * pr],     af, bt[0], bt[1]);
                mma16816(accO[2 * pr + 1], af, bt[2], bt[3]);
            }
        }
        __syncthreads();
        if (kt + 2 <= 15) LOAD_V(kt + 2, buf);
    }

#pragma unroll
    for (int e = 0; e < 2; e++) {
        rs[e] += __shfl_xor_sync(0xffffffffu, rs[e], 1);
        rs[e] += __shfl_xor_sync(0xffffffffu, rs[e], 2);
    }
    if ((lane & 3) == 0) {
#pragma unroll
        for (int e = 0; e < 2; e++)
            sRS[wn * 64 + wm * 16 + (lane >> 2) + 8 * e] = rs[e];
    }
    __syncthreads();

    const int b = bh >> 4, h = bh & 15;
#pragma unroll
    for (int half = 0; half < 2; half++) {
        const int row = wm * 16 + (lane >> 2) + 8 * half;
        const float inv = 1.0f / (sRS[row] + sRS[64 + row]);
        const int m = b * 1024 + (n0 + row);
        __half* ReRow = g_Acat + (size_t)m * K_EFF;
        __half* ImRow = g_Acat + (size_t)(m + 4096) * K_EFF;
#pragma unroll
        for (int nt = 0; nt < 8; nt++) {
            const int col = wn * 64 + nt * 8 + (lane & 3) * 2;
            const int d = col & 63;
            const int c = h * 64 + d;
            const float v0 = accO[nt][half * 2] * inv;
            const float v1 = accO[nt][half * 2 + 1] * inv;
            const __half2 hp = __floats2half2_rn(v0, v1);
            if (col < 64) {
                *(uint32_t*)(ReRow + c) = *(const uint32_t*)&hp;
                *(uint32_t*)(ImRow + 1024 + c) = *(const uint32_t*)&hp;
            } else {
                const __half2 hn = __hneg2(hp);
                *(uint32_t*)(ReRow + 1024 + c) = *(const uint32_t*)&hn;
                *(uint32_t*)(ImRow + c) = *(const uint32_t*)&hp;
            }
        }
    }
}

// ---------------- spin helper ----------------
__device__ __forceinline__ void wait_cnt(volatile int* c, int target)
{
    while (atomicAdd((int*)c, 0) < target) __nanosleep(128);
}

// =================== fat fused kernel ===================
// bids 0..1535: QKV GEMM (batch-major row order)
// bids 1536..2559: attention (batch-major)
// bids 2560..3071: out-proj GEMM (batch-major row order)
__global__ void __launch_bounds__(256, 2) fat_kernel(
    const float* __restrict__ biasR, const float* __restrict__ biasI,
    float* __restrict__ outR, float* __restrict__ outI)
{
    extern __shared__ char smem[];
    const int bid = blockIdx.x;
    const int tid = threadIdx.x;

    if (bid < 1536) {
        const int bx = bid % 24;
        const int rowblk = bid / 24;
        const int b = rowblk >> 4, sub = rowblk & 15;
        const int by = (sub < 8) ? (b * 8 + sub) : (32 + b * 8 + sub - 8);
        gemm_body(smem, 0, bx, by, biasR, biasI, outR, outI);
        __syncthreads();
        __threadfence();
        if (tid == 0) {
            const int layer = bx >> 3, colblk = bx & 7;
            atomicAdd(&g_cnt[b * 24 + layer * 8 + colblk], 1);
        }
    } else if (bid < 2560) {
        const int aid = bid - 1536;
        const int b = aid >> 8;
        const int rem = aid & 255;
        const int h = rem >> 4;
        const int ntile = rem & 15;
        if (tid == 0) {
            const int base = b * 24 + (h >> 1);
            wait_cnt(&g_cnt[base],      16);   // Q cols (layer 0)
            wait_cnt(&g_cnt[base + 8],  16);   // K cols (layer 1)
            wait_cnt(&g_cnt[base + 16], 16);   // V cols (layer 2)
            __threadfence();
        }
        __syncthreads();
        attn_body(smem, b * 16 + h, ntile * 64);
        __syncthreads();
        __threadfence();
        if (tid == 0) atomicAdd(&g_cnt[96 + b], 1);
    } else {
        const int oid = bid - 2560;
        const int bx = oid & 7;
        const int rowblk = oid >> 3;
        const int b = rowblk >> 4, sub = rowblk & 15;
        const int by = (sub < 8) ? (b * 8 + sub) : (32 + b * 8 + sub - 8);
        if (tid == 0) {
            wait_cnt(&g_cnt[96 + b], 256);
            __threadfence();
        }
        __syncthreads();
        gemm_body(smem, 1, bx, by, biasR + 3 * DIMV, biasI + 3 * DIMV, outR, outI);
    }
}

// =================== launcher ===================
extern "C" void kernel_launch(void* const* d_in, const int* in_sizes, int n_in,
                              void* d_out, int out_size)
{
    const float* xr = (const float*)d_in[0];
    const float* xi = (const float*)d_in[1];
    const float* Wr = (const float*)d_in[2];
    const float* Wi = (const float*)d_in[3];
    const float* br = (const float*)d_in[4];
    const float* bi = (const float*)d_in[5];

    float* outR = (float*)d_out;
    float* outI = outR + (size_t)BATCH * SEQ * DIMV;

    cudaFuncSetAttribute(fat_kernel, cudaFuncAttributeMaxDynamicSharedMemorySize, SMEM_GEMM);

    // build fp16 A and W operands + reset dependency counters
    conv_aw_kernel<<<8192, 256>>>(xr, xi, Wr, Wi);

    // fused QKV GEMM -> attention -> output projection, overlapped via counters
    fat_kernel<<<3072, 256, SMEM_GEMM>>>(br, bi, outR, outI);
}